// round 12
// baseline (speedup 1.0000x reference)
#include <cuda_runtime.h>

// DepthwiseRREUp: groups=C*G conv_transpose2d, kernel=stride=2, pad=0.
// out[b,c,g, 2i+di, 2j+dj] = x[b,c,g,i,j] * rot90(dw[c], g)[di][dj]
//
// x:  [B=8, C=256, G=4, H=64, W=64] fp32     (128 MiB, read once)
// dw: [C=256, 1, 2, 2] fp32                  (cache-resident)
// out:[B, C, G, 128, 128] fp32               (512 MiB, written once)
//
// PERSISTENT SLAB version of the best (R7, 101.5us) direct-STG kernel.
// (R10 submission of this scheme hit an infra failure — container died
// before any bench ran — so the theory is still untested; resubmitting.)
//
// Work unit ("task") = 4 consecutive output rows at one quad column:
//   2x LDG.64 (256 B/warp contiguous) + 4x STG.128 (512 B/warp contiguous).
// 256 consecutive tasks = one "group" = 16 KB contiguous output.
// Each of 1216 persistent CTAs (152 SMs x 8 CTAs, 2048 thr/SM) walks a
// CONTIGUOUS slab of ~27 groups sequentially, so every SM emits one long
// monotonic read stream and one long monotonic write stream for the whole
// kernel (DRAM row/page time-locality), instead of scheduler-ordered 16 KB
// hops. R8/R9 data: direct-STG path, all on-chip units idle, DRAM stuck at
// 78% / 6.24 TB/s; this tests the last untried variable (per-SM
// address-stream locality + full 2048 thr/SM occupancy).

__global__ void __launch_bounds__(256, 8)
DepthwiseRREUp_40106404610493_kernel(const float2* __restrict__ x2,
                                     const float4* __restrict__ dw4,  // [C] of (a,b,c,d)
                                     float4* __restrict__ out4,
                                     int ngroups, int ncta) {
    int bid = blockIdx.x;
    int g0 = (int)(((long long)bid       * ngroups) / ncta);
    int g1 = (int)(((long long)(bid + 1) * ngroups) / ncta);

    for (int grp = g0; grp < g1; ++grp) {
        int t = (grp << 8) + threadIdx.x;   // global task id

        int q     = t & 31;          // quad within output row == lane
        int rg    = t >> 5;          // row-group: 4 output rows
        int oi0   = (rg & 31) << 2;  // first output row (0..124, step 4)
        int plane = rg >> 5;         // linear (b,c,g)
        int g     = plane & 3;       // warp-uniform
        int c     = (plane >> 2) & 255;

        // Input rows oi0/2, oi0/2+1. Input plane = 2048 float2, 32 per row.
        const float2* xp = x2 + plane * 2048 + (oi0 >> 1) * 32 + q;
        float2 xa = __ldcs(xp);
        float2 xb = __ldcs(xp + 32);

        float4 w = dw4[c];  // a=w.x b=w.y c=w.z d=w.w (row-major 2x2)

        // numpy rot90 (CCW) k=g of [[a,b],[c,d]]:
        //   g=0: a b / c d    g=1: b d / a c
        //   g=2: d c / b a    g=3: c a / d b
        float f00, f01, f10, f11;
        switch (g) {
            case 0:  f00 = w.x; f01 = w.y; f10 = w.z; f11 = w.w; break;
            case 1:  f00 = w.y; f01 = w.w; f10 = w.x; f11 = w.z; break;
            case 2:  f00 = w.w; f01 = w.z; f10 = w.y; f11 = w.x; break;
            default: f00 = w.z; f01 = w.x; f10 = w.w; f11 = w.y; break;
        }

        // Output plane = 4096 float4, 32 per row.
        float4* op = out4 + plane * 4096 + oi0 * 32 + q;
        __stcs(op,      make_float4(xa.x * f00, xa.x * f01, xa.y * f00, xa.y * f01));
        __stcs(op + 32, make_float4(xa.x * f10, xa.x * f11, xa.y * f10, xa.y * f11));
        __stcs(op + 64, make_float4(xb.x * f00, xb.x * f01, xb.y * f00, xb.y * f01));
        __stcs(op + 96, make_float4(xb.x * f10, xb.x * f11, xb.y * f10, xb.y * f11));
    }
}

extern "C" void kernel_launch(void* const* d_in, const int* in_sizes, int n_in,
                              void* d_out, int out_size) {
    const float2* x2  = (const float2*)d_in[0];
    const float4* dw4 = (const float4*)d_in[1];
    float4* out4      = (float4*)d_out;

    int ntasks  = out_size / 16;      // 8,388,608 (4 output quads per task)
    int ngroups = ntasks / 256;       // 32,768 groups of 16 KB output each
    int ncta    = 152 * 8;            // GB300: 152 SMs x 8 CTAs (2048 thr/SM)
    if (ncta > ngroups) ncta = ngroups;

    DepthwiseRREUp_40106404610493_kernel<<<ncta, 256>>>(x2, dw4, out4, ngroups, ncta);
}

// round 13
// speedup vs baseline: 1.2102x; 1.2102x over previous
#include <cuda_runtime.h>

// DepthwiseRREUp: groups=C*G conv_transpose2d, kernel=stride=2, pad=0.
// out[b,c,g, 2i+di, 2j+dj] = x[b,c,g,i,j] * rot90(dw[c], g)[di][dj]
//
// x:  [B=8, C=256, G=4, H=64, W=64] fp32     (128 MiB, read once)
// dw: [C=256, 1, 2, 2] fp32                  (cache-resident)
// out:[B, C, G, 128, 128] fp32               (512 MiB, written once)
//
// Champion scheme (R8, 101.5us / DRAM 78.6%) with light tuning.
// Evidence across rounds: 4-row direct-STG (78.6%), 8-row (78.8%),
// SMEM+TMA bulk store (67.8%), persistent slabs (70.6%) -> achieved-HBM
// plateau ~6.24 TB/s for this 4:1 write:read mix; address-stream shaping
// is exhausted. This round: block=512, no tail guard (exact division),
// identical warp-level access pattern:
//   lane = output quad q; thread = 4 consecutive output rows at q.
//   2x LDG.64 (256 B/warp contiguous) + 4x STG.128 (512 B/warp contiguous),
//   all four stores contiguous 2 KB per warp, 32 KB contiguous per block,
//   sequential across blocks. Input read exactly once chip-wide.

__global__ void __launch_bounds__(512)
DepthwiseRREUp_40106404610493_kernel(const float2* __restrict__ x2,
                                     const float4* __restrict__ dw4,  // [C] of (a,b,c,d)
                                     float4* __restrict__ out4) {
    int t = blockIdx.x * 512 + threadIdx.x;

    int q     = t & 31;          // quad within output row == lane
    int rg    = t >> 5;          // row-group: 4 output rows
    int oi0   = (rg & 31) << 2;  // first output row (0..124, step 4)
    int plane = rg >> 5;         // linear (b,c,g)
    int g     = plane & 3;       // warp-uniform
    int c     = (plane >> 2) & 255;

    // Input rows oi0/2, oi0/2+1. Input plane = 2048 float2, 32 per row.
    const float2* xp = x2 + plane * 2048 + (oi0 >> 1) * 32 + q;
    float2 xa = __ldcs(xp);
    float2 xb = __ldcs(xp + 32);

    float4 w = dw4[c];  // a=w.x b=w.y c=w.z d=w.w (row-major 2x2)

    // numpy rot90 (CCW) k=g of [[a,b],[c,d]]:
    //   g=0: a b / c d    g=1: b d / a c
    //   g=2: d c / b a    g=3: c a / d b
    float f00, f01, f10, f11;
    switch (g) {
        case 0:  f00 = w.x; f01 = w.y; f10 = w.z; f11 = w.w; break;
        case 1:  f00 = w.y; f01 = w.w; f10 = w.x; f11 = w.z; break;
        case 2:  f00 = w.w; f01 = w.z; f10 = w.y; f11 = w.x; break;
        default: f00 = w.z; f01 = w.x; f10 = w.w; f11 = w.y; break;
    }

    // Output plane = 4096 float4, 32 per row.
    float4* op = out4 + plane * 4096 + oi0 * 32 + q;
    __stcs(op,      make_float4(xa.x * f00, xa.x * f01, xa.y * f00, xa.y * f01));
    __stcs(op + 32, make_float4(xa.x * f10, xa.x * f11, xa.y * f10, xa.y * f11));
    __stcs(op + 64, make_float4(xb.x * f00, xb.x * f01, xb.y * f00, xb.y * f01));
    __stcs(op + 96, make_float4(xb.x * f10, xb.x * f11, xb.y * f10, xb.y * f11));
}

extern "C" void kernel_launch(void* const* d_in, const int* in_sizes, int n_in,
                              void* d_out, int out_size) {
    const float2* x2  = (const float2*)d_in[0];
    const float4* dw4 = (const float4*)d_in[1];
    float4* out4      = (float4*)d_out;

    int nthreads = out_size / 16;     // 8,388,608 tasks (4 output quads each)
    int blocks   = nthreads / 512;    // exact: 16384 blocks
    DepthwiseRREUp_40106404610493_kernel<<<blocks, 512>>>(x2, dw4, out4);
}